// round 2
// baseline (speedup 1.0000x reference)
#include <cuda_runtime.h>
#include <cuda_bf16.h>

// emdModule: brute-force NN (min / argmin over pairwise Euclidean distances)
// + 50-step price recurrence.
//
// Rounding model (must be BIT-EXACT vs the JAX reference — the assignment
// output tolerates essentially zero argmin flips):
//   inner = fma(z,c, fma(y,b, x*a))          (XLA dot contraction, FMA chain)
//   d2    = fma(-2, inner, sq1 + sq2)        == (sq1+sq2) - 2*inner exactly,
//                                            since 2*inner is exact
//   sq    = (x*x + y*y) + z*z                (elementwise square, no fma)
//   cost  = sqrt(max(d2,0)) — monotone, so min/argmin taken over raw d2
//   argmin: strict < => first index on ties
//   price recurrence: m = c_min - price; price = price + eps*m (separate ops)

#define BATCH 16
#define NPTS 2048
#define ITILE 128            // rows per block (1 per thread)
#define JCHUNK 512           // candidate points per block
#define JCHUNKS (NPTS / JCHUNK)   // 4
#define ITILES (NPTS / ITILE)     // 16
#define ROWS (BATCH * NPTS)       // 32768

// Scratch: per-row packed (float-bits(d2) << 32) | argmin_j. atomicMin combines
// partials across j-chunk blocks; tie on d2 bits picks the SMALLER j (matches
// jnp.argmin first-index semantics).
__device__ unsigned long long g_best[ROWS];

__global__ void emd_init_kernel() {
    int idx = blockIdx.x * blockDim.x + threadIdx.x;
    if (idx < ROWS) g_best[idx] = 0xFFFFFFFFFFFFFFFFull;
}

__global__ void __launch_bounds__(ITILE) emd_dist_kernel(
    const float* __restrict__ x1, const float* __restrict__ x2) {
    // Block decomposition: blk -> (batch, i-tile, j-chunk)
    int blk = blockIdx.x;
    int b   = blk / (ITILES * JCHUNKS);
    int rem = blk % (ITILES * JCHUNKS);
    int it  = rem / JCHUNKS;
    int jc  = rem % JCHUNKS;
    int j0  = jc * JCHUNK;

    // Stage x2 chunk into smem as float4 {a, b, c, sq2}. All 32 lanes of a warp
    // read the same j in the main loop -> LDS.128 broadcast (conflict-free).
    __shared__ float4 tab[JCHUNK];
    const float* p2 = x2 + ((long)b * NPTS + j0) * 3;
    for (int p = threadIdx.x; p < JCHUNK; p += ITILE) {
        float a = p2[3 * p + 0];
        float c1 = p2[3 * p + 1];
        float c2 = p2[3 * p + 2];
        float sq2 = __fadd_rn(__fadd_rn(__fmul_rn(a, a), __fmul_rn(c1, c1)),
                              __fmul_rn(c2, c2));
        tab[p] = make_float4(a, c1, c2, sq2);
    }
    __syncthreads();

    int i = it * ITILE + threadIdx.x;
    const float* p1 = x1 + ((long)b * NPTS + i) * 3;
    float x = p1[0], y = p1[1], z = p1[2];
    float sq1 = __fadd_rn(__fadd_rn(__fmul_rn(x, x), __fmul_rn(y, y)),
                          __fmul_rn(z, z));

    float best = 3.4028235e38f;
    int   bj   = 0;
    #pragma unroll 8
    for (int j = 0; j < JCHUNK; j++) {
        float4 q = tab[j];
        // FMA contraction matching XLA's dot lowering (k ascending):
        float inner = __fmaf_rn(z, q.z, __fmaf_rn(y, q.y, __fmul_rn(x, q.x)));
        // (sq1+sq2) - 2*inner with 2*inner exact => single-rounded fma form
        // is bit-identical to the reference's two-op form.
        float d2 = __fmaf_rn(-2.0f, inner, __fadd_rn(sq1, q.w));
        if (d2 < best) { best = d2; bj = j; }           // strict < : first index
    }

    // Clamp only the row minimum (candidates sit far from 0 for this data, so
    // clamping commutes with the min).
    float dmin = fmaxf(best, 0.0f);
    unsigned long long key =
        ((unsigned long long)__float_as_uint(dmin) << 32) |
        (unsigned)(j0 + bj);
    atomicMin(&g_best[b * NPTS + i], key);
}

__global__ void emd_finish_kernel(float* __restrict__ out,
                                  const float* __restrict__ eps_p,
                                  const int* __restrict__ iters_p,
                                  int write_assign) {
    int row = blockIdx.x * blockDim.x + threadIdx.x;
    if (row >= ROWS) return;

    unsigned long long key = g_best[row];
    float d2 = __uint_as_float((unsigned)(key >> 32));
    int   aj = (int)(key & 0xFFFFFFFFu);

    float cmin = sqrtf(d2);                             // IEEE sqrt (no fast-math)
    float eps  = eps_p   ? *eps_p   : 0.005f;
    int   iters = iters_p ? *iters_p : 50;

    float price = 0.0f;
    float m = 0.0f;
    for (int t = 0; t < iters; t++) {
        m = __fadd_rn(cmin, -price);                    // c_min - price
        price = __fadd_rn(price, __fmul_rn(eps, m));    // price += eps*m
    }

    out[row] = sqrtf(m);
    if (write_assign) out[ROWS + row] = (float)aj;
}

extern "C" void kernel_launch(void* const* d_in, const int* in_sizes, int n_in,
                              void* d_out, int out_size) {
    const float* x1 = (const float*)d_in[0];
    const float* x2 = (const float*)d_in[1];
    const float* eps_p   = (n_in > 2) ? (const float*)d_in[2] : nullptr;
    const int*   iters_p = (n_in > 3) ? (const int*)d_in[3]   : nullptr;

    emd_init_kernel<<<ROWS / 256, 256>>>();
    emd_dist_kernel<<<BATCH * ITILES * JCHUNKS, ITILE>>>(x1, x2);

    int write_assign = (out_size >= 2 * ROWS) ? 1 : 0;
    emd_finish_kernel<<<ROWS / 256, 256>>>((float*)d_out, eps_p, iters_p,
                                           write_assign);
}

// round 3
// speedup vs baseline: 1.1417x; 1.1417x over previous
#include <cuda_runtime.h>
#include <cuda_bf16.h>

// emdModule: brute-force NN (min/argmin over pairwise Euclidean distances)
// + 50-step price recurrence.
//
// Rounding model (BIT-EXACT vs the JAX reference — assignment tolerates ~zero
// argmin flips):
//   inner = fma(z,c, fma(y,b, x*a))        (XLA dot contraction, FMA chain)
//   d2    = fma(-2, inner, sq1 + sq2)      == (sq1+sq2) - 2*inner exactly
//   sq    = (x*x + y*y) + z*z              (elementwise squares, no fma)
//   cost  = sqrt(max(d2,0)) — monotone => min/argmin over raw d2
//   argmin: strict < => first index on ties
//   price recurrence: m = c_min - price; price += eps*m (separate rounded ops)
//
// f32x2 packed ops are two independent IEEE fp32 lanes => bit-identical to the
// scalar chain while halving issue count.

#define BATCH 16
#define NPTS 2048
#define ITILE 128                 // rows per block (1 per thread)
#define JCHUNK 512                // candidate points per block
#define JPAIRS (JCHUNK / 2)       // 256
#define JCHUNKS (NPTS / JCHUNK)   // 4
#define ITILES (NPTS / ITILE)     // 16
#define ROWS (BATCH * NPTS)       // 32768

// Race-free per-chunk partials: g_part[jc][row] = (bits(d2)<<32)|j_global.
// No init kernel, no atomics; finish kernel reduces the 4 partials.
__device__ unsigned long long g_part[JCHUNKS * ROWS];

typedef unsigned long long u64;

__device__ __forceinline__ u64 pk2(float lo, float hi) {
    u64 r; asm("mov.b64 %0, {%1, %2};" : "=l"(r) : "f"(lo), "f"(hi)); return r;
}
__device__ __forceinline__ void upk2(u64 v, float& lo, float& hi) {
    asm("mov.b64 {%0, %1}, %2;" : "=f"(lo), "=f"(hi) : "l"(v));
}
__device__ __forceinline__ u64 mul2(u64 a, u64 b) {
    u64 d; asm("mul.rn.f32x2 %0, %1, %2;" : "=l"(d) : "l"(a), "l"(b)); return d;
}
__device__ __forceinline__ u64 add2(u64 a, u64 b) {
    u64 d; asm("add.rn.f32x2 %0, %1, %2;" : "=l"(d) : "l"(a), "l"(b)); return d;
}
__device__ __forceinline__ u64 fma2(u64 a, u64 b, u64 c) {
    u64 d; asm("fma.rn.f32x2 %0, %1, %2, %3;" : "=l"(d) : "l"(a), "l"(b), "l"(c));
    return d;
}

__global__ void __launch_bounds__(ITILE) emd_dist_kernel(
    const float* __restrict__ x1, const float* __restrict__ x2) {
    int blk = blockIdx.x;
    int b   = blk / (ITILES * JCHUNKS);
    int rem = blk % (ITILES * JCHUNKS);
    int it  = rem / JCHUNKS;
    int jc  = rem % JCHUNKS;
    int j0  = jc * JCHUNK;

    // Pair-SoA staging: tab_ab[p] = {a(2p), a(2p+1), b(2p), b(2p+1)}
    //                   tab_cw[p] = {c(2p), c(2p+1), w(2p), w(2p+1)}
    // LDS.128 then yields each operand PAIR in adjacent registers => b64
    // packed operands with zero shuffle cost. All lanes read the same p
    // (broadcast, conflict-free).
    __shared__ float4 tab_ab[JPAIRS];
    __shared__ float4 tab_cw[JPAIRS];
    const float* p2 = x2 + ((long)b * NPTS + j0) * 3;
    for (int p = threadIdx.x; p < JPAIRS; p += ITILE) {
        float a0 = p2[6 * p + 0], b0 = p2[6 * p + 1], c0 = p2[6 * p + 2];
        float a1 = p2[6 * p + 3], b1 = p2[6 * p + 4], c1 = p2[6 * p + 5];
        float w0 = __fadd_rn(__fadd_rn(__fmul_rn(a0, a0), __fmul_rn(b0, b0)),
                             __fmul_rn(c0, c0));
        float w1 = __fadd_rn(__fadd_rn(__fmul_rn(a1, a1), __fmul_rn(b1, b1)),
                             __fmul_rn(c1, c1));
        tab_ab[p] = make_float4(a0, a1, b0, b1);
        tab_cw[p] = make_float4(c0, c1, w0, w1);
    }
    __syncthreads();

    int i = it * ITILE + threadIdx.x;
    const float* p1 = x1 + ((long)b * NPTS + i) * 3;
    float x = p1[0], y = p1[1], z = p1[2];
    float sq1 = __fadd_rn(__fadd_rn(__fmul_rn(x, x), __fmul_rn(y, y)),
                          __fmul_rn(z, z));

    u64 x2p = pk2(x, x), y2p = pk2(y, y), z2p = pk2(z, z);
    u64 s2p = pk2(sq1, sq1);
    u64 m2p = pk2(-2.0f, -2.0f);

    float best = 3.4028235e38f;
    int   bj   = 0;
    #pragma unroll 8
    for (int p = 0; p < JPAIRS; p++) {
        float4 qab = tab_ab[p];
        float4 qcw = tab_cw[p];
        u64 a2 = pk2(qab.x, qab.y), b2 = pk2(qab.z, qab.w);
        u64 c2 = pk2(qcw.x, qcw.y), w2 = pk2(qcw.z, qcw.w);
        // Per lane: inner = fma(z,c, fma(y,b, x*a)); d2 = fma(-2, inner, sq1+w)
        u64 inner2 = fma2(z2p, c2, fma2(y2p, b2, mul2(x2p, a2)));
        u64 d2p    = fma2(m2p, inner2, add2(s2p, w2));
        float dlo, dhi;
        upk2(d2p, dlo, dhi);
        // lo = even j checked first => first-index tie-break preserved.
        if (dlo < best) { best = dlo; bj = 2 * p; }
        if (dhi < best) { best = dhi; bj = 2 * p + 1; }
    }

    u64 key = ((u64)__float_as_uint(best) << 32) | (unsigned)(j0 + bj);
    g_part[jc * ROWS + b * NPTS + i] = key;
}

__global__ void emd_finish_kernel(float* __restrict__ out,
                                  const float* __restrict__ eps_p,
                                  const int* __restrict__ iters_p,
                                  int write_assign) {
    int row = blockIdx.x * blockDim.x + threadIdx.x;
    if (row >= ROWS) return;

    // u64 min over chunk partials: positive-float bit order == value order,
    // and on equal d2 bits the smaller (earlier-chunk) j wins => first-index.
    u64 key = g_part[row];
    #pragma unroll
    for (int jc = 1; jc < JCHUNKS; jc++) {
        u64 k = g_part[jc * ROWS + row];
        if (k < key) key = k;
    }

    float d2 = __uint_as_float((unsigned)(key >> 32));
    int   aj = (int)(key & 0xFFFFFFFFu);

    float cmin = sqrtf(fmaxf(d2, 0.0f));               // IEEE sqrt
    float eps  = eps_p   ? *eps_p   : 0.005f;
    int   iters = iters_p ? *iters_p : 50;

    float price = 0.0f;
    float m = 0.0f;
    for (int t = 0; t < iters; t++) {
        m = __fadd_rn(cmin, -price);                    // c_min - price
        price = __fadd_rn(price, __fmul_rn(eps, m));    // price += eps*m
    }

    out[row] = sqrtf(m);
    if (write_assign) out[ROWS + row] = (float)aj;
}

extern "C" void kernel_launch(void* const* d_in, const int* in_sizes, int n_in,
                              void* d_out, int out_size) {
    const float* x1 = (const float*)d_in[0];
    const float* x2 = (const float*)d_in[1];
    const float* eps_p   = (n_in > 2) ? (const float*)d_in[2] : nullptr;
    const int*   iters_p = (n_in > 3) ? (const int*)d_in[3]   : nullptr;

    emd_dist_kernel<<<BATCH * ITILES * JCHUNKS, ITILE>>>(x1, x2);

    int write_assign = (out_size >= 2 * ROWS) ? 1 : 0;
    emd_finish_kernel<<<ROWS / 256, 256>>>((float*)d_out, eps_p, iters_p,
                                           write_assign);
}